// round 1
// baseline (speedup 1.0000x reference)
#include <cuda_runtime.h>

#define BB 4
#define CC 32
#define HH 512
#define WW 960
#define HT 128
#define WT 240
#define HW (HH * WW)
#define THW (HT * WT)

__global__ __launch_bounds__(256) void tile_warp_kernel(
    const float* __restrict__ tp,   // tile_plane [B,3,HT,WT]
    const float* __restrict__ fl,   // fea_l [B,C,H,W]
    const float* __restrict__ fr,   // fea_r [B,C,H,W]
    float* __restrict__ out)        // [B,48,HT,WT]
{
    int idx = blockIdx.x * blockDim.x + threadIdx.x;
    if (idx >= BB * HH * WW) return;

    int x = idx % WW;
    int t = idx / WW;
    int y = t % HH;
    int b = t / HH;

    int tx = x >> 2, ty = y >> 2;
    int j = x & 3,  i = y & 3;

    // tile plane params
    int tbase = b * 3 * THW + ty * WT + tx;
    float d   = __ldg(tp + tbase);
    float ddx = __ldg(tp + tbase + THW);
    float ddy = __ldg(tp + tbase + 2 * THW);

    // slanted-plane disparity at full res (center offset (ts-1)/2 = 1.5)
    float disp = d + ((float)i - 1.5f) * ddy + ((float)j - 1.5f) * ddx;
    float s = (float)x - disp;          // x_src for disp_d = 0
    float f0f = floorf(s);
    float w = s - f0f;                  // identical fraction for all 3 levels
    int f0 = (int)f0f;

    const float WM1 = (float)(WW - 1);
    // validity per disparity level: x_src_l = s - l, l in {-1,0,+1}
    bool vm = (s + 1.0f >= 0.0f) && (s + 1.0f <= WM1);  // disp_d = -1
    bool v0 = (s >= 0.0f)        && (s <= WM1);          // disp_d =  0
    bool vp = (s - 1.0f >= 0.0f) && (s - 1.0f <= WM1);   // disp_d = +1

    // 4 consecutive taps cover x0/x1 of all three levels
    int i0 = min(max(f0 - 1, 0), WW - 1);
    int i1 = min(max(f0,     0), WW - 1);
    int i2 = min(max(f0 + 1, 0), WW - 1);
    int i3 = min(max(f0 + 2, 0), WW - 1);

    const float* lp = fl + (b * CC * HH + y) * WW + x;
    const float* rp = fr + (b * CC * HH + y) * WW;

    float am = 0.0f, a0 = 0.0f, ap = 0.0f;

    #pragma unroll 8
    for (int c = 0; c < CC; c++) {
        int co = c * HW;
        float flv = __ldg(lp + co);
        float q0 = __ldg(rp + co + i0);
        float q1 = __ldg(rp + co + i1);
        float q2 = __ldg(rp + co + i2);
        float q3 = __ldg(rp + co + i3);

        // disp_d=-1: floor = f0+1 -> taps (q2,q3); 0 -> (q1,q2); +1 -> (q0,q1)
        float wm = fmaf(w, q3 - q2, q2);
        float w0 = fmaf(w, q2 - q1, q1);
        float wp = fmaf(w, q1 - q0, q0);

        float afl = fabsf(flv);
        am += vm ? fabsf(flv - wm) : afl;
        a0 += v0 ? fabsf(flv - w0) : afl;
        ap += vp ? fabsf(flv - wp) : afl;
    }

    // tile-unshuffle channel = i*ts + j; level blocks of 16 channels
    int ch = i * 4 + j;
    int obase = (b * 48) * THW + ty * WT + tx;
    out[obase + (ch)      * THW] = am;
    out[obase + (16 + ch) * THW] = a0;
    out[obase + (32 + ch) * THW] = ap;
}

extern "C" void kernel_launch(void* const* d_in, const int* in_sizes, int n_in,
                              void* d_out, int out_size) {
    const float* tp = (const float*)d_in[0];
    const float* fl = (const float*)d_in[1];
    const float* fr = (const float*)d_in[2];
    float* out = (float*)d_out;

    int total = BB * HH * WW;
    int block = 256;
    int grid = (total + block - 1) / block;
    tile_warp_kernel<<<grid, block>>>(tp, fl, fr, out);
}